// round 12
// baseline (speedup 1.0000x reference)
#include <cuda_runtime.h>
#include <math.h>

#define CEPS 1e-5f

typedef unsigned long long u64;

__device__ __forceinline__ u64 pk2(float lo, float hi) {
    u64 r;
    asm("mov.b64 %0, {%1, %2};" : "=l"(r) : "r"(__float_as_uint(lo)), "r"(__float_as_uint(hi)));
    return r;
}
__device__ __forceinline__ void upk2(u64 v, float& lo, float& hi) {
    unsigned int a, b;
    asm("mov.b64 {%0, %1}, %2;" : "=r"(a), "=r"(b) : "l"(v));
    lo = __uint_as_float(a); hi = __uint_as_float(b);
}
__device__ __forceinline__ u64 fma2(u64 a, u64 b, u64 c) {
    u64 d;
    asm("fma.rn.f32x2 %0, %1, %2, %3;" : "=l"(d) : "l"(a), "l"(b), "l"(c));
    return d;
}
__device__ __forceinline__ u64 add2(u64 a, u64 b) {
    u64 d;
    asm("add.rn.f32x2 %0, %1, %2;" : "=l"(d) : "l"(a), "l"(b));
    return d;
}

// ---------------- device scratch (allocation-free) ----------------
__device__ float g_YSC [8*128*32*128];   // shortcut RAW (pre-BN) (b,o,n,d)
__device__ float g_X1  [8*64*32*128];    // l1 output RAW (pre-BN) (b,c,n,d)
__device__ float g_ADJ [512*1024];       // corr NUMERATOR (sign == corr sign)
__device__ float g_MEAN[512*32];         // per-(b,m) row means (BN'd)
__device__ float g_WR  [512*32];         // reduced W_fc1
__device__ float g_HS  [512*512];        // h = relu(WR @ mean)
__device__ float g_E2  [4*512*1024];     // fc2 split-K partials (4)
__device__ float g_AOUT[8*64*32*128];    // attention output RAW (b,m,i,d)
__device__ float g_COUT[8*32*64*128];    // conv output RAW (b,n,m,d)
__device__ float g_ssc[128], g_qsc[128];
__device__ float g_s1 [64],  g_q1 [64];
__device__ float g_s2 [64],  g_q2 [64];
__device__ float g_s3 [32],  g_q3 [32];

// ---------------- K0: blocks 0..63 -> W_fc1 reduce; block 64 -> zero stats
__global__ void __launch_bounds__(256) k_initwred(const float* __restrict__ Wfc1) {
    __shared__ float ws[8*1024];
    const int tid = threadIdx.x;
    if (blockIdx.x == 64) {
        if (tid < 128) { g_ssc[tid] = 0.f; g_qsc[tid] = 0.f; }
        if (tid < 64)  { g_s1[tid] = 0.f; g_q1[tid] = 0.f; g_s2[tid] = 0.f; g_q2[tid] = 0.f; }
        if (tid < 32)  { g_s3[tid] = 0.f; g_q3[tid] = 0.f; }
        return;
    }
    const float4* wp = (const float4*)(Wfc1 + (size_t)blockIdx.x * 8192);
    for (int i = tid; i < 2048; i += 256) ((float4*)ws)[i] = wp[i];
    __syncthreads();
    const int rr = tid >> 5, i = tid & 31;
    const float* row = ws + rr*1024;
    float rs = 0.f, cs = 0.f;
    #pragma unroll 8
    for (int j = 0; j < 32; j++) {
        rs += row[i*32 + j];
        cs += row[j*32 + i];
    }
    g_WR[(blockIdx.x*8 + rr)*32 + i] = fmaf(0.5f, rs, cs) - 0.5f*row[i*33];
}

// ---------------- K1: YSC[b,o,n,d] = sum_m Wsc[o,m] x[b,n,m,d]; X1 likewise with Wl1
__global__ void __launch_bounds__(256) k1_matmul(const float* __restrict__ x,
                                                 const float* __restrict__ Wsc,
                                                 const float* __restrict__ Wl1) {
    __shared__ float xs[64*128];
    __shared__ float wst[64*64];
    const int bn = blockIdx.x;
    const int chunk = blockIdx.y;
    const int tid = threadIdx.x;
    const float* xp = x + (size_t)bn * 8192;
    #pragma unroll
    for (int i = 0; i < 32; i++) xs[tid + i*256] = xp[tid + i*256];
    const float* wp = (chunk < 2) ? (Wsc + chunk*4096) : Wl1;
    #pragma unroll
    for (int i = tid; i < 1024; i += 256) {
        float4 v = ((const float4*)wp)[i];
        int o = i >> 4, m4 = (i & 15) * 4;
        wst[(m4+0)*64 + o] = v.x;
        wst[(m4+1)*64 + o] = v.y;
        wst[(m4+2)*64 + o] = v.z;
        wst[(m4+3)*64 + o] = v.w;
    }
    __syncthreads();
    const int lane = tid & 31;
    const int grp  = tid >> 5;
    const int d0 = lane * 4;
    u64 acc[4][4];
    #pragma unroll
    for (int i = 0; i < 4; i++)
        #pragma unroll
        for (int j = 0; j < 4; j++) acc[i][j] = 0ull;
    #pragma unroll 4
    for (int m = 0; m < 64; m++) {
        float4 xv = *(const float4*)&xs[m*128 + d0];
        u64 xd0 = pk2(xv.x, xv.x), xd1 = pk2(xv.y, xv.y);
        u64 xd2 = pk2(xv.z, xv.z), xd3 = pk2(xv.w, xv.w);
        ulonglong2 w01 = *(const ulonglong2*)&wst[m*64 + grp*8];
        ulonglong2 w23 = *(const ulonglong2*)&wst[m*64 + grp*8 + 4];
        acc[0][0]=fma2(w01.x,xd0,acc[0][0]); acc[0][1]=fma2(w01.x,xd1,acc[0][1]);
        acc[0][2]=fma2(w01.x,xd2,acc[0][2]); acc[0][3]=fma2(w01.x,xd3,acc[0][3]);
        acc[1][0]=fma2(w01.y,xd0,acc[1][0]); acc[1][1]=fma2(w01.y,xd1,acc[1][1]);
        acc[1][2]=fma2(w01.y,xd2,acc[1][2]); acc[1][3]=fma2(w01.y,xd3,acc[1][3]);
        acc[2][0]=fma2(w23.x,xd0,acc[2][0]); acc[2][1]=fma2(w23.x,xd1,acc[2][1]);
        acc[2][2]=fma2(w23.x,xd2,acc[2][2]); acc[2][3]=fma2(w23.x,xd3,acc[2][3]);
        acc[3][0]=fma2(w23.y,xd0,acc[3][0]); acc[3][1]=fma2(w23.y,xd1,acc[3][1]);
        acc[3][2]=fma2(w23.y,xd2,acc[3][2]); acc[3][3]=fma2(w23.y,xd3,acc[3][3]);
    }
    const int b = bn >> 5, n = bn & 31;
    float* sArr = (chunk < 2) ? g_ssc : g_s1;
    float* qArr = (chunk < 2) ? g_qsc : g_q1;
    const int cbase = (chunk == 1) ? 64 : 0;
    #pragma unroll
    for (int kp = 0; kp < 4; kp++) {
        float lo0,hi0,lo1,hi1,lo2,hi2,lo3,hi3;
        upk2(acc[kp][0], lo0, hi0); upk2(acc[kp][1], lo1, hi1);
        upk2(acc[kp][2], lo2, hi2); upk2(acc[kp][3], lo3, hi3);
        float sl = lo0+lo1+lo2+lo3, sh = hi0+hi1+hi2+hi3;
        float ql = lo0*lo0+lo1*lo1+lo2*lo2+lo3*lo3;
        float qh = hi0*hi0+hi1*hi1+hi2*hi2+hi3*hi3;
        #pragma unroll
        for (int off = 16; off > 0; off >>= 1) {
            sl += __shfl_down_sync(0xffffffffu, sl, off);
            sh += __shfl_down_sync(0xffffffffu, sh, off);
            ql += __shfl_down_sync(0xffffffffu, ql, off);
            qh += __shfl_down_sync(0xffffffffu, qh, off);
        }
        int cloc = grp*8 + kp*2;
        if (lane == 0) {
            atomicAdd(&sArr[cbase + cloc],     sl);
            atomicAdd(&qArr[cbase + cloc],     ql);
            atomicAdd(&sArr[cbase + cloc + 1], sh);
            atomicAdd(&qArr[cbase + cloc + 1], qh);
        }
        float4 flo = make_float4(lo0, lo1, lo2, lo3);
        float4 fhi = make_float4(hi0, hi1, hi2, hi3);
        if (chunk < 2) {
            int o = chunk*64 + cloc;
            float* op0 = g_YSC + ((((size_t)b*128 + o)*32 + n) << 7);
            float* op1 = g_YSC + ((((size_t)b*128 + o + 1)*32 + n) << 7);
            *(float4*)&op0[d0] = flo;
            *(float4*)&op1[d0] = fhi;
        } else {
            float* op0 = g_X1 + ((((size_t)b*64 + cloc)*32 + n) << 7);
            float* op1 = g_X1 + ((((size_t)b*64 + cloc + 1)*32 + n) << 7);
            *(float4*)&op0[d0] = flo;
            *(float4*)&op1[d0] = fhi;
        }
    }
}

// ---------------- attention part 1: SYRK corr numerator, in-warp d-group reduction; BN1 fold
__global__ void __launch_bounds__(256) k_att1(const float* __restrict__ g1,
                                              const float* __restrict__ b1) {
    __shared__ float xsT[128*34];
    __shared__ float mean[32];
    const int bm = blockIdx.x;
    const int tid = threadIdx.x;
    const int c = bm & 63;
    const float m1 = g_s1[c] * (1.f/32768.f);
    const float v1 = g_q1[c] * (1.f/32768.f) - m1*m1;
    const float sc = g1[c] * rsqrtf(v1 + CEPS);
    const float sh = b1[c] - m1 * sc;
    const float4* xp4 = (const float4*)(g_X1 + (size_t)bm * 4096);
    const int warp = tid >> 5, lane = tid & 31;
    #pragma unroll
    for (int iter = 0; iter < 4; iter++) {
        int r = warp + iter*8;
        float4 v = xp4[r*32 + lane];
        v.x = fmaf(v.x, sc, sh); v.y = fmaf(v.y, sc, sh);
        v.z = fmaf(v.z, sc, sh); v.w = fmaf(v.w, sc, sh);
        int dd = lane * 4;
        xsT[(dd+0)*34 + r] = v.x;
        xsT[(dd+1)*34 + r] = v.y;
        xsT[(dd+2)*34 + r] = v.z;
        xsT[(dd+3)*34 + r] = v.w;
        float s = v.x+v.y+v.z+v.w;
        #pragma unroll
        for (int off = 16; off > 0; off >>= 1)
            s += __shfl_down_sync(0xffffffffu, s, off);
        if (lane == 0) {
            float m = s * (1.f/128.f);
            mean[r] = m;
            g_MEAN[bm*32 + r] = m;
        }
    }
    __syncthreads();
    const int dg = lane >> 3;
    const int i0 = warp * 4;
    const int j0 = (lane & 7) * 4;
    u64 acc[4][2];
    #pragma unroll
    for (int ii = 0; ii < 4; ii++) { acc[ii][0] = 0ull; acc[ii][1] = 0ull; }
    #pragma unroll 4
    for (int q = 0; q < 32; q++) {
        const float* row = xsT + (dg + q*4)*34;
        u64 a01 = *(const u64*)&row[i0];
        u64 a23 = *(const u64*)&row[i0+2];
        u64 b01 = *(const u64*)&row[j0];
        u64 b23 = *(const u64*)&row[j0+2];
        float ax, ay, az, aw;
        upk2(a01, ax, ay); upk2(a23, az, aw);
        u64 A0 = pk2(ax,ax), A1 = pk2(ay,ay), A2 = pk2(az,az), A3 = pk2(aw,aw);
        acc[0][0]=fma2(A0,b01,acc[0][0]); acc[0][1]=fma2(A0,b23,acc[0][1]);
        acc[1][0]=fma2(A1,b01,acc[1][0]); acc[1][1]=fma2(A1,b23,acc[1][1]);
        acc[2][0]=fma2(A2,b01,acc[2][0]); acc[2][1]=fma2(A2,b23,acc[2][1]);
        acc[3][0]=fma2(A3,b01,acc[3][0]); acc[3][1]=fma2(A3,b23,acc[3][1]);
    }
    #pragma unroll
    for (int ii = 0; ii < 4; ii++)
        #pragma unroll
        for (int jj = 0; jj < 2; jj++) {
            acc[ii][jj] = add2(acc[ii][jj], __shfl_down_sync(0xffffffffu, acc[ii][jj], 16));
            acc[ii][jj] = add2(acc[ii][jj], __shfl_down_sync(0xffffffffu, acc[ii][jj], 8));
        }
    if (lane < 8) {
        #pragma unroll
        for (int ii = 0; ii < 4; ii++) {
            int i = i0 + ii;
            float mi128 = 128.f * mean[i];
            float d0v, d1v, d2v, d3v;
            upk2(acc[ii][0], d0v, d1v);
            upk2(acc[ii][1], d2v, d3v);
            float a0 = d0v - mi128*mean[j0];
            float a1 = d1v - mi128*mean[j0+1];
            float a2 = d2v - mi128*mean[j0+2];
            float a3 = d3v - mi128*mean[j0+3];
            *(float4*)&g_ADJ[(size_t)bm*1024 + i*32 + j0] = make_float4(a0, a1, a2, a3);
        }
    }
}

// ---------------- HS[bm,r] = relu(sum_i WR[r,i] * MEAN[bm,i]); 32x32 tiles, grid 256
__global__ void __launch_bounds__(256) k_hsmall() {
    __shared__ float ms[32*36];
    __shared__ float ws[32*36];
    const int tid = threadIdx.x;
    const int bm0 = (blockIdx.x >> 4) * 32;
    const int r0  = (blockIdx.x & 15) * 32;
    for (int i = tid; i < 1024; i += 256) {
        int r = i >> 5, k = i & 31;
        ms[r*36 + k] = g_MEAN[(bm0 + r)*32 + k];
        ws[r*36 + k] = g_WR[(r0 + r)*32 + k];
    }
    __syncthreads();
    const int tm = tid >> 3;          // bm row 0..31
    const int tn = (tid & 7) * 4;     // 4 r outputs
    float4 a[8];
    #pragma unroll
    for (int q = 0; q < 8; q++) a[q] = *(const float4*)&ms[tm*36 + q*4];
    float acc[4];
    #pragma unroll
    for (int p = 0; p < 4; p++) {
        const float4* w = (const float4*)&ws[(tn + p)*36];
        float s = 0.f;
        #pragma unroll
        for (int q = 0; q < 8; q++) {
            float4 wv = w[q];
            s = fmaf(a[q].x, wv.x, s);
            s = fmaf(a[q].y, wv.y, s);
            s = fmaf(a[q].z, wv.z, s);
            s = fmaf(a[q].w, wv.w, s);
        }
        acc[p] = fmaxf(s, 0.f);
    }
    *(float4*)&g_HS[(size_t)(bm0 + tm)*512 + r0 + tn] = make_float4(acc[0], acc[1], acc[2], acc[3]);
}

// ---------------- split-K f32x2 NT GEMM (GEMM2 only)
__global__ void __launch_bounds__(128) k_gemm(const float* __restrict__ A,
                                              const float* __restrict__ Bm,
                                              float* __restrict__ C,
                                              int Nn, int Ktot, int klen) {
    __shared__ float As[32*64];
    __shared__ float Bs[32*68];
    const int tid = threadIdx.x;
    const int n0 = blockIdx.x * 64;
    const int m0 = blockIdx.y * 64;
    const int kbeg = blockIdx.z * klen;
    const int tn = tid & 15;
    const int tm = tid >> 4;
    const int sr = tid >> 1;
    const int kq = (tid & 1) * 16;
    u64 acc[8][2];
    #pragma unroll
    for (int i = 0; i < 8; i++) { acc[i][0] = 0ull; acc[i][1] = 0ull; }
    for (int k0 = kbeg; k0 < kbeg + klen; k0 += 32) {
        const float* ap = &A[(size_t)(m0 + sr)*Ktot + k0 + kq];
        const float* bp = &Bm[(size_t)(n0 + sr)*Ktot + k0 + kq];
        #pragma unroll
        for (int j = 0; j < 4; j++) {
            float4 av = *(const float4*)(ap + j*4);
            As[(kq+j*4+0)*64 + sr] = av.x;
            As[(kq+j*4+1)*64 + sr] = av.y;
            As[(kq+j*4+2)*64 + sr] = av.z;
            As[(kq+j*4+3)*64 + sr] = av.w;
            float4 bv = *(const float4*)(bp + j*4);
            Bs[(kq+j*4+0)*68 + sr] = bv.x;
            Bs[(kq+j*4+1)*68 + sr] = bv.y;
            Bs[(kq+j*4+2)*68 + sr] = bv.z;
            Bs[(kq+j*4+3)*68 + sr] = bv.w;
        }
        __syncthreads();
        #pragma unroll 8
        for (int kk = 0; kk < 32; kk++) {
            float4 a0 = *(const float4*)&As[kk*64 + tm*8];
            float4 a1 = *(const float4*)&As[kk*64 + tm*8 + 4];
            ulonglong2 b = *(const ulonglong2*)&Bs[kk*68 + tn*4];
            u64 A0 = pk2(a0.x, a0.x), A1 = pk2(a0.y, a0.y);
            u64 A2 = pk2(a0.z, a0.z), A3 = pk2(a0.w, a0.w);
            u64 A4 = pk2(a1.x, a1.x), A5 = pk2(a1.y, a1.y);
            u64 A6 = pk2(a1.z, a1.z), A7 = pk2(a1.w, a1.w);
            acc[0][0]=fma2(A0,b.x,acc[0][0]); acc[0][1]=fma2(A0,b.y,acc[0][1]);
            acc[1][0]=fma2(A1,b.x,acc[1][0]); acc[1][1]=fma2(A1,b.y,acc[1][1]);
            acc[2][0]=fma2(A2,b.x,acc[2][0]); acc[2][1]=fma2(A2,b.y,acc[2][1]);
            acc[3][0]=fma2(A3,b.x,acc[3][0]); acc[3][1]=fma2(A3,b.y,acc[3][1]);
            acc[4][0]=fma2(A4,b.x,acc[4][0]); acc[4][1]=fma2(A4,b.y,acc[4][1]);
            acc[5][0]=fma2(A5,b.x,acc[5][0]); acc[5][1]=fma2(A5,b.y,acc[5][1]);
            acc[6][0]=fma2(A6,b.x,acc[6][0]); acc[6][1]=fma2(A6,b.y,acc[6][1]);
            acc[7][0]=fma2(A7,b.x,acc[7][0]); acc[7][1]=fma2(A7,b.y,acc[7][1]);
        }
        __syncthreads();
    }
    float* Cz = C + (size_t)blockIdx.z * 512 * Nn;
    #pragma unroll
    for (int i = 0; i < 8; i++) {
        float l0,h0,l1,h1;
        upk2(acc[i][0], l0, h0);
        upk2(acc[i][1], l1, h1);
        *(float4*)&Cz[(size_t)(m0 + tm*8 + i)*Nn + n0 + tn*4] = make_float4(l0, h0, l1, h1);
    }
}

// ---------------- attention part 2: masked softmax + att@x (j-outer f32x2 apply); BN1 fold
__global__ void __launch_bounds__(256) k_att2(const float* __restrict__ g1,
                                              const float* __restrict__ b1) {
    __shared__ float xs[32*132];
    __shared__ float att[32*36];
    __shared__ float red[256], redq[256];
    const int bm = blockIdx.x;
    const int tid = threadIdx.x;
    const int c = bm & 63;
    const float m1 = g_s1[c] * (1.f/32768.f);
    const float v1 = g_q1[c] * (1.f/32768.f) - m1*m1;
    const float sc = g1[c] * rsqrtf(v1 + CEPS);
    const float sh = b1[c] - m1 * sc;
    const float4* xp4 = (const float4*)(g_X1 + (size_t)bm * 4096);
    for (int i4 = tid; i4 < 1024; i4 += 256) {
        int r = i4 >> 5, d = (i4 & 31) * 4;
        float4 v = xp4[i4];
        v.x = fmaf(v.x, sc, sh); v.y = fmaf(v.y, sc, sh);
        v.z = fmaf(v.z, sc, sh); v.w = fmaf(v.w, sc, sh);
        *(float4*)&xs[r*132 + d] = v;
    }
    const int warp = tid >> 5, lane = tid & 31;
    for (int r = warp; r < 32; r += 8) {
        size_t idx = (size_t)bm*1024 + r*32 + lane;
        float adj = g_ADJ[idx];
        float pre = g_E2[idx] + g_E2[idx + 524288]
                  + g_E2[idx + 1048576] + g_E2[idx + 1572864];
        float e2v = 1.f / (1.f + __expf(-pre));
        float v = (adj > 0.f) ? e2v : -1e12f;
        float mx = v;
        #pragma unroll
        for (int off = 16; off > 0; off >>= 1) mx = fmaxf(mx, __shfl_xor_sync(0xffffffffu, mx, off));
        float ex = __expf(v - mx);
        float s = ex;
        #pragma unroll
        for (int off = 16; off > 0; off >>= 1) s += __shfl_xor_sync(0xffffffffu, s, off);
        att[r*36 + lane] = ex / s;
    }
    __syncthreads();
    const int dp = tid & 63;
    const int ih = tid >> 6;
    u64 acc[8];
    #pragma unroll
    for (int k = 0; k < 8; k++) acc[k] = 0ull;
    #pragma unroll 4
    for (int j = 0; j < 32; j++) {
        u64 xj = *(const u64*)&xs[j*132 + dp*2];
        #pragma unroll
        for (int k = 0; k < 8; k++) {
            float a = att[(ih + k*4)*36 + j];
            acc[k] = fma2(pk2(a, a), xj, acc[k]);
        }
    }
    float ts = 0.f, tq = 0.f;
    #pragma unroll
    for (int k = 0; k < 8; k++) {
        int i = ih + k*4;
        float lo, hi; upk2(acc[k], lo, hi);
        *(float2*)&g_AOUT[(size_t)bm*4096 + i*128 + dp*2] = make_float2(lo, hi);
        ts += lo + hi;
        tq = fmaf(lo, lo, fmaf(hi, hi, tq));
    }
    red[tid] = ts; redq[tid] = tq;
    __syncthreads();
    for (int off = 128; off > 0; off >>= 1) {
        if (tid < off) { red[tid] += red[tid+off]; redq[tid] += redq[tid+off]; }
        __syncthreads();
    }
    if (tid == 0) { atomicAdd(&g_s2[c], red[0]); atomicAdd(&g_q2[c], redq[0]); }
}

// ---------------- depthwise 3x3 conv per (b,n); column halves, padded 66x66 tile
__global__ void __launch_bounds__(256) k_conv(const float* __restrict__ Wdw,
                                              const float* __restrict__ g2,
                                              const float* __restrict__ b2) {
    __shared__ float ts[66*68];
    __shared__ float sscale[64], sshift[64];
    __shared__ float red[256], redq[256];
    const int bn = blockIdx.x;
    const int xh = blockIdx.y;
    const int base = xh * 64;
    const int b = bn >> 5, n = bn & 31;
    const int tid = threadIdx.x;
    if (tid < 64) {
        float m = g_s2[tid] * (1.f/32768.f);
        float v = g_q2[tid] * (1.f/32768.f) - m*m;
        float s = g2[tid] * rsqrtf(v + CEPS);
        sscale[tid] = s;
        sshift[tid] = b2[tid] - m * s;
    }
    for (int i = tid; i < 66*68; i += 256) ts[i] = 0.f;
    __syncthreads();
    for (int i = tid; i < 64*66; i += 256) {
        int m = i / 66, dc = i % 66;
        int d = base - 1 + dc;
        if (d >= 0 && d < 128) {
            float v = g_AOUT[((((size_t)b*64 + m)*32 + n) << 7) + d];
            ts[(m+1)*68 + dc] = fmaxf(fmaf(v, sscale[m], sshift[m]), 0.f);
        }
    }
    float w[9];
    #pragma unroll
    for (int t = 0; t < 9; t++) w[t] = Wdw[n*9 + t];
    __syncthreads();
    float as = 0.f, aq = 0.f;
    for (int i = tid; i < 4096; i += 256) {
        int y = i >> 6, xc = i & 63;
        const float* cptr = &ts[(y+1)*68 + xc + 1];
        float acc;
        acc = w[0]*cptr[-69];
        acc = fmaf(w[1], cptr[-68], acc);
        acc = fmaf(w[2], cptr[-67], acc);
        acc = fmaf(w[3], cptr[-1],  acc);
        acc = fmaf(w[4], cptr[0],   acc);
        acc = fmaf(w[5], cptr[1],   acc);
        acc = fmaf(w[6], cptr[67],  acc);
        acc = fmaf(w[7], cptr[68],  acc);
        acc = fmaf(w[8], cptr[69],  acc);
        g_COUT[(size_t)bn*8192 + y*128 + base + xc] = acc;
        as += acc; aq = fmaf(acc, acc, aq);
    }
    red[tid] = as; redq[tid] = aq;
    __syncthreads();
    for (int off = 128; off > 0; off >>= 1) {
        if (tid < off) { red[tid] += red[tid+off]; redq[tid] += redq[tid+off]; }
        __syncthreads();
    }
    if (tid == 0) { atomicAdd(&g_s3[n], red[0]); atomicAdd(&g_q3[n], redq[0]); }
}

// ---------------- final: out[b,n,o,d] = sum_m Wl3[o,m]*relu(bn3(cout)) + bnsc(YSC raw)
__global__ void __launch_bounds__(256) k_final(const float* __restrict__ Wl3,
                                               const float* __restrict__ g3, const float* __restrict__ b3,
                                               const float* __restrict__ gsc, const float* __restrict__ bsc,
                                               float* __restrict__ outp) {
    __shared__ float cs[64*128];
    __shared__ float wst[64*64];
    __shared__ float cscale[128], cshift[128];
    const int bn = blockIdx.x;
    const int half = blockIdx.y;
    const int tid = threadIdx.x;
    const int b = bn >> 5, n = bn & 31;
    if (tid < 128) {
        float m = g_ssc[tid] * (1.f/32768.f);
        float v = g_qsc[tid] * (1.f/32768.f) - m*m;
        float s = gsc[tid] * rsqrtf(v + CEPS);
        cscale[tid] = s;
        cshift[tid] = bsc[tid] - m * s;
    }
    float m3 = g_s3[n] * (1.f/65536.f);
    float v3 = g_q3[n] * (1.f/65536.f) - m3*m3;
    float scale = g3[n] * rsqrtf(v3 + CEPS);
    float shift = b3[n] - m3 * scale;
    const float* cp = g_COUT + (size_t)bn * 8192;
    #pragma unroll
    for (int i = 0; i < 32; i++)
        cs[tid + i*256] = fmaxf(fmaf(cp[tid + i*256], scale, shift), 0.f);
    const float* wp = Wl3 + half*4096;
    #pragma unroll
    for (int i = tid; i < 1024; i += 256) {
        float4 v = ((const float4*)wp)[i];
        int o = i >> 4, m4 = (i & 15) * 4;
        wst[(m4+0)*64 + o] = v.x;
        wst[(m4+1)*64 + o] = v.y;
        wst[(m4+2)*64 + o] = v.z;
        wst[(m4+3)*64 + o] = v.w;
    }
    __syncthreads();
    const int lane = tid & 31, grp = tid >> 5;
    const int d0 = lane * 4;
    u64 acc[4][4];
    #pragma unroll
    for (int i = 0; i < 4; i++)
        #pragma unroll
        for (int j = 0; j < 4; j++) acc[i][j] = 0ull;
    #pragma unroll 4
    for (int m = 0; m < 64; m++) {
        float4 xv = *(const float4*)&cs[m*128 + d0];
        u64 xd0 = pk2(xv.x, xv.x), xd1 = pk2(xv.y, xv.y);
        u64 xd2 = pk2(xv.z, xv.z), xd3 = pk2(xv.w, xv.w);
        ulonglong2 w01 = *(const ulonglong2*)&wst[m*64 + grp*8];
        ulonglong2 w23 = *(const ulonglong2*)&wst[m*64 + grp*8 + 4];
        acc[0][0]=fma2(w01.x,xd0,acc[0][0]); acc[0][1]=fma2(w01.x,xd1,acc[0][1]);
        acc[0][2]=fma2(w01.x,xd2,acc[0][2]); acc[0][3]=fma2(w01.x,xd3,acc[0][3]);
        acc[1][0]=fma2(w01.y,xd0,acc[1][0]); acc[1][1]=fma2(w01.y,xd1,acc[1][1]);
        acc[1][2]=fma2(w01.y,xd2,acc[1][2]); acc[1][3]=fma2(w01.y,xd3,acc[1][3]);
        acc[2][0]=fma2(w23.x,xd0,acc[2][0]); acc[2][1]=fma2(w23.x,xd1,acc[2][1]);
        acc[2][2]=fma2(w23.x,xd2,acc[2][2]); acc[2][3]=fma2(w23.x,xd3,acc[2][3]);
        acc[3][0]=fma2(w23.y,xd0,acc[3][0]); acc[3][1]=fma2(w23.y,xd1,acc[3][1]);
        acc[3][2]=fma2(w23.y,xd2,acc[3][2]); acc[3][3]=fma2(w23.y,xd3,acc[3][3]);
    }
    #pragma unroll
    for (int kp = 0; kp < 4; kp++) {
        int o = half*64 + grp*8 + kp*2;
        float lo0,hi0,lo1,hi1,lo2,hi2,lo3,hi3;
        upk2(acc[kp][0], lo0, hi0); upk2(acc[kp][1], lo1, hi1);
        upk2(acc[kp][2], lo2, hi2); upk2(acc[kp][3], lo3, hi3);
        const float* scp0 = g_YSC + ((((size_t)b*128 + o)*32 + n) << 7);
        const float* scp1 = g_YSC + ((((size_t)b*128 + o + 1)*32 + n) << 7);
        float* op0 = outp + ((((size_t)b*32 + n)*128 + o) << 7);
        float* op1 = outp + ((((size_t)b*32 + n)*128 + o + 1) << 7);
        float4 s0 = *(const float4*)&scp0[d0];
        float4 s1 = *(const float4*)&scp1[d0];
        float sca0 = cscale[o],   shf0 = cshift[o];
        float sca1 = cscale[o+1], shf1 = cshift[o+1];
        *(float4*)&op0[d0] = make_float4(lo0 + fmaf(s0.x, sca0, shf0),
                                         lo1 + fmaf(s0.y, sca0, shf0),
                                         lo2 + fmaf(s0.z, sca0, shf0),
                                         lo3 + fmaf(s0.w, sca0, shf0));
        *(float4*)&op1[d0] = make_float4(hi0 + fmaf(s1.x, sca1, shf1),
                                         hi1 + fmaf(s1.y, sca1, shf1),
                                         hi2 + fmaf(s1.z, sca1, shf1),
                                         hi3 + fmaf(s1.w, sca1, shf1));
    }
}

// ---------------- launcher ----------------
extern "C" void kernel_launch(void* const* d_in, const int* in_sizes, int n_in,
                              void* d_out, int out_size) {
    const float* x    = (const float*)d_in[0];
    const float* Wsc  = (const float*)d_in[1];
    const float* gsc  = (const float*)d_in[2];
    const float* bsc  = (const float*)d_in[3];
    const float* Wl1  = (const float*)d_in[4];
    const float* g1   = (const float*)d_in[5];
    const float* b1   = (const float*)d_in[6];
    const float* Wfc1 = (const float*)d_in[7];
    const float* Wfc2 = (const float*)d_in[8];
    const float* g2   = (const float*)d_in[9];
    const float* b2   = (const float*)d_in[10];
    const float* Wdw  = (const float*)d_in[11];
    const float* g3   = (const float*)d_in[12];
    const float* b3   = (const float*)d_in[13];
    const float* Wl3  = (const float*)d_in[14];
    float* outp = (float*)d_out;

    float *hs, *e2;
    cudaGetSymbolAddress((void**)&hs, g_HS);
    cudaGetSymbolAddress((void**)&e2, g_E2);

    k_initwred<<<65, 256>>>(Wfc1);
    k1_matmul<<<dim3(256, 3), 256>>>(x, Wsc, Wl1);
    k_att1<<<512, 256>>>(g1, b1);
    k_hsmall<<<256, 256>>>();
    k_gemm<<<dim3(16, 8, 4), 128>>>(hs, Wfc2, e2, 1024, 512, 128);
    k_att2<<<512, 256>>>(g1, b1);
    k_conv<<<dim3(256, 2), 256>>>(Wdw, g2, b2);
    k_final<<<dim3(256, 2), 256>>>(Wl3, g3, b3, gsc, bsc, outp);
}

// round 13
// speedup vs baseline: 1.0263x; 1.0263x over previous
#include <cuda_runtime.h>
#include <math.h>

#define CEPS 1e-5f

typedef unsigned long long u64;

__device__ __forceinline__ u64 pk2(float lo, float hi) {
    u64 r;
    asm("mov.b64 %0, {%1, %2};" : "=l"(r) : "r"(__float_as_uint(lo)), "r"(__float_as_uint(hi)));
    return r;
}
__device__ __forceinline__ void upk2(u64 v, float& lo, float& hi) {
    unsigned int a, b;
    asm("mov.b64 {%0, %1}, %2;" : "=r"(a), "=r"(b) : "l"(v));
    lo = __uint_as_float(a); hi = __uint_as_float(b);
}
__device__ __forceinline__ u64 fma2(u64 a, u64 b, u64 c) {
    u64 d;
    asm("fma.rn.f32x2 %0, %1, %2, %3;" : "=l"(d) : "l"(a), "l"(b), "l"(c));
    return d;
}
__device__ __forceinline__ u64 add2(u64 a, u64 b) {
    u64 d;
    asm("add.rn.f32x2 %0, %1, %2;" : "=l"(d) : "l"(a), "l"(b));
    return d;
}

// ---------------- device scratch (allocation-free) ----------------
__device__ float g_YSC [8*128*32*128];
__device__ float g_X1  [8*64*32*128];
__device__ float g_ADJ [512*1024];       // corr numerator (sign == corr sign)
__device__ float g_MEAN[512*32];
__device__ float g_WR  [512*32];
__device__ float g_HS  [512*512];
__device__ float g_E2  [4*512*1024];
__device__ float g_AOUT[8*64*32*128];
__device__ float g_COUT[8*32*64*128];
__device__ float g_ssc[128], g_qsc[128];
__device__ float g_s1 [64],  g_q1 [64];
__device__ float g_s2 [64],  g_q2 [64];
__device__ float g_s3 [32],  g_q3 [32];

// ---------------- zero stats (pre-fork)
__global__ void k_zero() {
    int t = threadIdx.x;
    if (t < 128) { g_ssc[t] = 0.f; g_qsc[t] = 0.f; }
    if (t < 64)  { g_s1[t] = 0.f; g_q1[t] = 0.f; g_s2[t] = 0.f; g_q2[t] = 0.f; }
    if (t < 32)  { g_s3[t] = 0.f; g_q3[t] = 0.f; }
}

// ---------------- W_fc1 reduce (side stream)
__global__ void __launch_bounds__(256) k_wred(const float* __restrict__ Wfc1) {
    __shared__ float ws[8*1024];
    const int tid = threadIdx.x;
    const float4* wp = (const float4*)(Wfc1 + (size_t)blockIdx.x * 8192);
    for (int i = tid; i < 2048; i += 256) ((float4*)ws)[i] = wp[i];
    __syncthreads();
    const int rr = tid >> 5, i = tid & 31;
    const float* row = ws + rr*1024;
    float rs = 0.f, cs = 0.f;
    #pragma unroll 8
    for (int j = 0; j < 32; j++) {
        rs += row[i*32 + j];
        cs += row[j*32 + i];
    }
    g_WR[(blockIdx.x*8 + rr)*32 + i] = fmaf(0.5f, rs, cs) - 0.5f*row[i*33];
}

// ---------------- K1: chunk = chunkBase + blockIdx.y; 0,1 -> Wsc->YSC; 2 -> W->X1
__global__ void __launch_bounds__(256) k1_matmul(const float* __restrict__ x,
                                                 const float* __restrict__ W,
                                                 int chunkBase) {
    __shared__ float xs[64*128];
    __shared__ float wst[64*64];
    const int bn = blockIdx.x;
    const int chunk = chunkBase + blockIdx.y;
    const int tid = threadIdx.x;
    const float* xp = x + (size_t)bn * 8192;
    #pragma unroll
    for (int i = 0; i < 32; i++) xs[tid + i*256] = xp[tid + i*256];
    const float* wp = (chunk < 2) ? (W + chunk*4096) : W;
    #pragma unroll
    for (int i = tid; i < 1024; i += 256) {
        float4 v = ((const float4*)wp)[i];
        int o = i >> 4, m4 = (i & 15) * 4;
        wst[(m4+0)*64 + o] = v.x;
        wst[(m4+1)*64 + o] = v.y;
        wst[(m4+2)*64 + o] = v.z;
        wst[(m4+3)*64 + o] = v.w;
    }
    __syncthreads();
    const int lane = tid & 31;
    const int grp  = tid >> 5;
    const int d0 = lane * 4;
    u64 acc[4][4];
    #pragma unroll
    for (int i = 0; i < 4; i++)
        #pragma unroll
        for (int j = 0; j < 4; j++) acc[i][j] = 0ull;
    #pragma unroll 4
    for (int m = 0; m < 64; m++) {
        float4 xv = *(const float4*)&xs[m*128 + d0];
        u64 xd0 = pk2(xv.x, xv.x), xd1 = pk2(xv.y, xv.y);
        u64 xd2 = pk2(xv.z, xv.z), xd3 = pk2(xv.w, xv.w);
        ulonglong2 w01 = *(const ulonglong2*)&wst[m*64 + grp*8];
        ulonglong2 w23 = *(const ulonglong2*)&wst[m*64 + grp*8 + 4];
        acc[0][0]=fma2(w01.x,xd0,acc[0][0]); acc[0][1]=fma2(w01.x,xd1,acc[0][1]);
        acc[0][2]=fma2(w01.x,xd2,acc[0][2]); acc[0][3]=fma2(w01.x,xd3,acc[0][3]);
        acc[1][0]=fma2(w01.y,xd0,acc[1][0]); acc[1][1]=fma2(w01.y,xd1,acc[1][1]);
        acc[1][2]=fma2(w01.y,xd2,acc[1][2]); acc[1][3]=fma2(w01.y,xd3,acc[1][3]);
        acc[2][0]=fma2(w23.x,xd0,acc[2][0]); acc[2][1]=fma2(w23.x,xd1,acc[2][1]);
        acc[2][2]=fma2(w23.x,xd2,acc[2][2]); acc[2][3]=fma2(w23.x,xd3,acc[2][3]);
        acc[3][0]=fma2(w23.y,xd0,acc[3][0]); acc[3][1]=fma2(w23.y,xd1,acc[3][1]);
        acc[3][2]=fma2(w23.y,xd2,acc[3][2]); acc[3][3]=fma2(w23.y,xd3,acc[3][3]);
    }
    const int b = bn >> 5, n = bn & 31;
    float* sArr = (chunk < 2) ? g_ssc : g_s1;
    float* qArr = (chunk < 2) ? g_qsc : g_q1;
    const int cbase = (chunk == 1) ? 64 : 0;
    #pragma unroll
    for (int kp = 0; kp < 4; kp++) {
        float lo0,hi0,lo1,hi1,lo2,hi2,lo3,hi3;
        upk2(acc[kp][0], lo0, hi0); upk2(acc[kp][1], lo1, hi1);
        upk2(acc[kp][2], lo2, hi2); upk2(acc[kp][3], lo3, hi3);
        float sl = lo0+lo1+lo2+lo3, sh = hi0+hi1+hi2+hi3;
        float ql = lo0*lo0+lo1*lo1+lo2*lo2+lo3*lo3;
        float qh = hi0*hi0+hi1*hi1+hi2*hi2+hi3*hi3;
        #pragma unroll
        for (int off = 16; off > 0; off >>= 1) {
            sl += __shfl_down_sync(0xffffffffu, sl, off);
            sh += __shfl_down_sync(0xffffffffu, sh, off);
            ql += __shfl_down_sync(0xffffffffu, ql, off);
            qh += __shfl_down_sync(0xffffffffu, qh, off);
        }
        int cloc = grp*8 + kp*2;
        if (lane == 0) {
            atomicAdd(&sArr[cbase + cloc],     sl);
            atomicAdd(&qArr[cbase + cloc],     ql);
            atomicAdd(&sArr[cbase + cloc + 1], sh);
            atomicAdd(&qArr[cbase + cloc + 1], qh);
        }
        float4 flo = make_float4(lo0, lo1, lo2, lo3);
        float4 fhi = make_float4(hi0, hi1, hi2, hi3);
        if (chunk < 2) {
            int o = chunk*64 + cloc;
            float* op0 = g_YSC + ((((size_t)b*128 + o)*32 + n) << 7);
            float* op1 = g_YSC + ((((size_t)b*128 + o + 1)*32 + n) << 7);
            *(float4*)&op0[d0] = flo;
            *(float4*)&op1[d0] = fhi;
        } else {
            float* op0 = g_X1 + ((((size_t)b*64 + cloc)*32 + n) << 7);
            float* op1 = g_X1 + ((((size_t)b*64 + cloc + 1)*32 + n) << 7);
            *(float4*)&op0[d0] = flo;
            *(float4*)&op1[d0] = fhi;
        }
    }
}

// ---------------- attention part 1 (R11 version, unchanged)
__global__ void __launch_bounds__(256) k_att1(const float* __restrict__ g1,
                                              const float* __restrict__ b1) {
    __shared__ float xsT[128*34];
    __shared__ float mean[32];
    const int bm = blockIdx.x;
    const int tid = threadIdx.x;
    const int c = bm & 63;
    const float m1 = g_s1[c] * (1.f/32768.f);
    const float v1 = g_q1[c] * (1.f/32768.f) - m1*m1;
    const float sc = g1[c] * rsqrtf(v1 + CEPS);
    const float sh = b1[c] - m1 * sc;
    const float4* xp4 = (const float4*)(g_X1 + (size_t)bm * 4096);
    const int warp = tid >> 5, lane = tid & 31;
    #pragma unroll
    for (int iter = 0; iter < 4; iter++) {
        int r = warp + iter*8;
        float4 v = xp4[r*32 + lane];
        v.x = fmaf(v.x, sc, sh); v.y = fmaf(v.y, sc, sh);
        v.z = fmaf(v.z, sc, sh); v.w = fmaf(v.w, sc, sh);
        int dd = lane * 4;
        xsT[(dd+0)*34 + r] = v.x;
        xsT[(dd+1)*34 + r] = v.y;
        xsT[(dd+2)*34 + r] = v.z;
        xsT[(dd+3)*34 + r] = v.w;
        float s = v.x+v.y+v.z+v.w;
        #pragma unroll
        for (int off = 16; off > 0; off >>= 1)
            s += __shfl_down_sync(0xffffffffu, s, off);
        if (lane == 0) {
            float m = s * (1.f/128.f);
            mean[r] = m;
            g_MEAN[bm*32 + r] = m;
        }
    }
    __syncthreads();
    const int dg = lane >> 3;
    const int i0 = warp * 4;
    const int j0 = (lane & 7) * 4;
    u64 acc[4][2];
    #pragma unroll
    for (int ii = 0; ii < 4; ii++) { acc[ii][0] = 0ull; acc[ii][1] = 0ull; }
    #pragma unroll 4
    for (int q = 0; q < 32; q++) {
        const float* row = xsT + (dg + q*4)*34;
        u64 a01 = *(const u64*)&row[i0];
        u64 a23 = *(const u64*)&row[i0+2];
        u64 b01 = *(const u64*)&row[j0];
        u64 b23 = *(const u64*)&row[j0+2];
        float ax, ay, az, aw;
        upk2(a01, ax, ay); upk2(a23, az, aw);
        u64 A0 = pk2(ax,ax), A1 = pk2(ay,ay), A2 = pk2(az,az), A3 = pk2(aw,aw);
        acc[0][0]=fma2(A0,b01,acc[0][0]); acc[0][1]=fma2(A0,b23,acc[0][1]);
        acc[1][0]=fma2(A1,b01,acc[1][0]); acc[1][1]=fma2(A1,b23,acc[1][1]);
        acc[2][0]=fma2(A2,b01,acc[2][0]); acc[2][1]=fma2(A2,b23,acc[2][1]);
        acc[3][0]=fma2(A3,b01,acc[3][0]); acc[3][1]=fma2(A3,b23,acc[3][1]);
    }
    #pragma unroll
    for (int ii = 0; ii < 4; ii++)
        #pragma unroll
        for (int jj = 0; jj < 2; jj++) {
            acc[ii][jj] = add2(acc[ii][jj], __shfl_down_sync(0xffffffffu, acc[ii][jj], 16));
            acc[ii][jj] = add2(acc[ii][jj], __shfl_down_sync(0xffffffffu, acc[ii][jj], 8));
        }
    if (lane < 8) {
        #pragma unroll
        for (int ii = 0; ii < 4; ii++) {
            int i = i0 + ii;
            float mi128 = 128.f * mean[i];
            float d0v, d1v, d2v, d3v;
            upk2(acc[ii][0], d0v, d1v);
            upk2(acc[ii][1], d2v, d3v);
            float a0 = d0v - mi128*mean[j0];
            float a1 = d1v - mi128*mean[j0+1];
            float a2 = d2v - mi128*mean[j0+2];
            float a3 = d3v - mi128*mean[j0+3];
            *(float4*)&g_ADJ[(size_t)bm*1024 + i*32 + j0] = make_float4(a0, a1, a2, a3);
        }
    }
}

// ---------------- HS (R11 version, 64 blocks)
__global__ void __launch_bounds__(256) k_hsmall() {
    __shared__ float ms[64*32];
    __shared__ float ws[64*32];
    const int tid = threadIdx.x;
    const int bm0 = (blockIdx.x >> 3) * 64;
    const int r0  = (blockIdx.x & 7) * 64;
    for (int i = tid; i < 512; i += 256) {
        ((float4*)ms)[i] = ((const float4*)(g_MEAN + bm0*32))[i];
        ((float4*)ws)[i] = ((const float4*)(g_WR + r0*32))[i];
    }
    __syncthreads();
    const int tm = tid >> 4;
    const int tn = tid & 15;
    float acc[4][4];
    #pragma unroll
    for (int q = 0; q < 4; q++)
        #pragma unroll
        for (int p = 0; p < 4; p++) acc[q][p] = 0.f;
    #pragma unroll 8
    for (int k = 0; k < 32; k++) {
        float a0 = ms[(tm*4+0)*32 + k], a1 = ms[(tm*4+1)*32 + k];
        float a2 = ms[(tm*4+2)*32 + k], a3 = ms[(tm*4+3)*32 + k];
        float w0 = ws[(tn*4+0)*32 + k], w1 = ws[(tn*4+1)*32 + k];
        float w2 = ws[(tn*4+2)*32 + k], w3 = ws[(tn*4+3)*32 + k];
        acc[0][0]=fmaf(a0,w0,acc[0][0]); acc[0][1]=fmaf(a0,w1,acc[0][1]);
        acc[0][2]=fmaf(a0,w2,acc[0][2]); acc[0][3]=fmaf(a0,w3,acc[0][3]);
        acc[1][0]=fmaf(a1,w0,acc[1][0]); acc[1][1]=fmaf(a1,w1,acc[1][1]);
        acc[1][2]=fmaf(a1,w2,acc[1][2]); acc[1][3]=fmaf(a1,w3,acc[1][3]);
        acc[2][0]=fmaf(a2,w0,acc[2][0]); acc[2][1]=fmaf(a2,w1,acc[2][1]);
        acc[2][2]=fmaf(a2,w2,acc[2][2]); acc[2][3]=fmaf(a2,w3,acc[2][3]);
        acc[3][0]=fmaf(a3,w0,acc[3][0]); acc[3][1]=fmaf(a3,w1,acc[3][1]);
        acc[3][2]=fmaf(a3,w2,acc[3][2]); acc[3][3]=fmaf(a3,w3,acc[3][3]);
    }
    #pragma unroll
    for (int q = 0; q < 4; q++) {
        float4 r4 = make_float4(fmaxf(acc[q][0],0.f), fmaxf(acc[q][1],0.f),
                                fmaxf(acc[q][2],0.f), fmaxf(acc[q][3],0.f));
        *(float4*)&g_HS[(size_t)(bm0 + tm*4 + q)*512 + r0 + tn*4] = r4;
    }
}

// ---------------- split-K f32x2 NT GEMM (GEMM2)
__global__ void __launch_bounds__(128) k_gemm(const float* __restrict__ A,
                                              const float* __restrict__ Bm,
                                              float* __restrict__ C,
                                              int Nn, int Ktot, int klen) {
    __shared__ float As[32*64];
    __shared__ float Bs[32*68];
    const int tid = threadIdx.x;
    const int n0 = blockIdx.x * 64;
    const int m0 = blockIdx.y * 64;
    const int kbeg = blockIdx.z * klen;
    const int tn = tid & 15;
    const int tm = tid >> 4;
    const int sr = tid >> 1;
    const int kq = (tid & 1) * 16;
    u64 acc[8][2];
    #pragma unroll
    for (int i = 0; i < 8; i++) { acc[i][0] = 0ull; acc[i][1] = 0ull; }
    for (int k0 = kbeg; k0 < kbeg + klen; k0 += 32) {
        const float* ap = &A[(size_t)(m0 + sr)*Ktot + k0 + kq];
        const float* bp = &Bm[(size_t)(n0 + sr)*Ktot + k0 + kq];
        #pragma unroll
        for (int j = 0; j < 4; j++) {
            float4 av = *(const float4*)(ap + j*4);
            As[(kq+j*4+0)*64 + sr] = av.x;
            As[(kq+j*4+1)*64 + sr] = av.y;
            As[(kq+j*4+2)*64 + sr] = av.z;
            As[(kq+j*4+3)*64 + sr] = av.w;
            float4 bv = *(const float4*)(bp + j*4);
            Bs[(kq+j*4+0)*68 + sr] = bv.x;
            Bs[(kq+j*4+1)*68 + sr] = bv.y;
            Bs[(kq+j*4+2)*68 + sr] = bv.z;
            Bs[(kq+j*4+3)*68 + sr] = bv.w;
        }
        __syncthreads();
        #pragma unroll 8
        for (int kk = 0; kk < 32; kk++) {
            float4 a0 = *(const float4*)&As[kk*64 + tm*8];
            float4 a1 = *(const float4*)&As[kk*64 + tm*8 + 4];
            ulonglong2 b = *(const ulonglong2*)&Bs[kk*68 + tn*4];
            u64 A0 = pk2(a0.x, a0.x), A1 = pk2(a0.y, a0.y);
            u64 A2 = pk2(a0.z, a0.z), A3 = pk2(a0.w, a0.w);
            u64 A4 = pk2(a1.x, a1.x), A5 = pk2(a1.y, a1.y);
            u64 A6 = pk2(a1.z, a1.z), A7 = pk2(a1.w, a1.w);
            acc[0][0]=fma2(A0,b.x,acc[0][0]); acc[0][1]=fma2(A0,b.y,acc[0][1]);
            acc[1][0]=fma2(A1,b.x,acc[1][0]); acc[1][1]=fma2(A1,b.y,acc[1][1]);
            acc[2][0]=fma2(A2,b.x,acc[2][0]); acc[2][1]=fma2(A2,b.y,acc[2][1]);
            acc[3][0]=fma2(A3,b.x,acc[3][0]); acc[3][1]=fma2(A3,b.y,acc[3][1]);
            acc[4][0]=fma2(A4,b.x,acc[4][0]); acc[4][1]=fma2(A4,b.y,acc[4][1]);
            acc[5][0]=fma2(A5,b.x,acc[5][0]); acc[5][1]=fma2(A5,b.y,acc[5][1]);
            acc[6][0]=fma2(A6,b.x,acc[6][0]); acc[6][1]=fma2(A6,b.y,acc[6][1]);
            acc[7][0]=fma2(A7,b.x,acc[7][0]); acc[7][1]=fma2(A7,b.y,acc[7][1]);
        }
        __syncthreads();
    }
    float* Cz = C + (size_t)blockIdx.z * 512 * Nn;
    #pragma unroll
    for (int i = 0; i < 8; i++) {
        float l0,h0,l1,h1;
        upk2(acc[i][0], l0, h0);
        upk2(acc[i][1], l1, h1);
        *(float4*)&Cz[(size_t)(m0 + tm*8 + i)*Nn + n0 + tn*4] = make_float4(l0, h0, l1, h1);
    }
}

// ---------------- attention part 2 (j-outer apply, R11 version)
__global__ void __launch_bounds__(256) k_att2(const float* __restrict__ g1,
                                              const float* __restrict__ b1) {
    __shared__ float xs[32*132];
    __shared__ float att[32*36];
    __shared__ float red[256], redq[256];
    const int bm = blockIdx.x;
    const int tid = threadIdx.x;
    const int c = bm & 63;
    const float m1 = g_s1[c] * (1.f/32768.f);
    const float v1 = g_q1[c] * (1.f/32768.f) - m1*m1;
    const float sc = g1[c] * rsqrtf(v1 + CEPS);
    const float sh = b1[c] - m1 * sc;
    const float4* xp4 = (const float4*)(g_X1 + (size_t)bm * 4096);
    for (int i4 = tid; i4 < 1024; i4 += 256) {
        int r = i4 >> 5, d = (i4 & 31) * 4;
        float4 v = xp4[i4];
        v.x = fmaf(v.x, sc, sh); v.y = fmaf(v.y, sc, sh);
        v.z = fmaf(v.z, sc, sh); v.w = fmaf(v.w, sc, sh);
        *(float4*)&xs[r*132 + d] = v;
    }
    const int warp = tid >> 5, lane = tid & 31;
    for (int r = warp; r < 32; r += 8) {
        size_t idx = (size_t)bm*1024 + r*32 + lane;
        float adj = g_ADJ[idx];
        float pre = g_E2[idx] + g_E2[idx + 524288]
                  + g_E2[idx + 1048576] + g_E2[idx + 1572864];
        float e2v = 1.f / (1.f + __expf(-pre));
        float v = (adj > 0.f) ? e2v : -1e12f;
        float mx = v;
        #pragma unroll
        for (int off = 16; off > 0; off >>= 1) mx = fmaxf(mx, __shfl_xor_sync(0xffffffffu, mx, off));
        float ex = __expf(v - mx);
        float s = ex;
        #pragma unroll
        for (int off = 16; off > 0; off >>= 1) s += __shfl_xor_sync(0xffffffffu, s, off);
        att[r*36 + lane] = ex / s;
    }
    __syncthreads();
    const int dp = tid & 63;
    const int ih = tid >> 6;
    u64 acc[8];
    #pragma unroll
    for (int k = 0; k < 8; k++) acc[k] = 0ull;
    #pragma unroll 4
    for (int j = 0; j < 32; j++) {
        u64 xj = *(const u64*)&xs[j*132 + dp*2];
        #pragma unroll
        for (int k = 0; k < 8; k++) {
            float a = att[(ih + k*4)*36 + j];
            acc[k] = fma2(pk2(a, a), xj, acc[k]);
        }
    }
    float ts = 0.f, tq = 0.f;
    #pragma unroll
    for (int k = 0; k < 8; k++) {
        int i = ih + k*4;
        float lo, hi; upk2(acc[k], lo, hi);
        *(float2*)&g_AOUT[(size_t)bm*4096 + i*128 + dp*2] = make_float2(lo, hi);
        ts += lo + hi;
        tq = fmaf(lo, lo, fmaf(hi, hi, tq));
    }
    red[tid] = ts; redq[tid] = tq;
    __syncthreads();
    for (int off = 128; off > 0; off >>= 1) {
        if (tid < off) { red[tid] += red[tid+off]; redq[tid] += redq[tid+off]; }
        __syncthreads();
    }
    if (tid == 0) { atomicAdd(&g_s2[c], red[0]); atomicAdd(&g_q2[c], redq[0]); }
}

// ---------------- depthwise conv (column halves, R11 version)
__global__ void __launch_bounds__(256) k_conv(const float* __restrict__ Wdw,
                                              const float* __restrict__ g2,
                                              const float* __restrict__ b2) {
    __shared__ float ts[66*68];
    __shared__ float sscale[64], sshift[64];
    __shared__ float red[256], redq[256];
    const int bn = blockIdx.x;
    const int xh = blockIdx.y;
    const int base = xh * 64;
    const int b = bn >> 5, n = bn & 31;
    const int tid = threadIdx.x;
    if (tid < 64) {
        float m = g_s2[tid] * (1.f/32768.f);
        float v = g_q2[tid] * (1.f/32768.f) - m*m;
        float s = g2[tid] * rsqrtf(v + CEPS);
        sscale[tid] = s;
        sshift[tid] = b2[tid] - m * s;
    }
    for (int i = tid; i < 66*68; i += 256) ts[i] = 0.f;
    __syncthreads();
    for (int i = tid; i < 64*66; i += 256) {
        int m = i / 66, dc = i % 66;
        int d = base - 1 + dc;
        if (d >= 0 && d < 128) {
            float v = g_AOUT[((((size_t)b*64 + m)*32 + n) << 7) + d];
            ts[(m+1)*68 + dc] = fmaxf(fmaf(v, sscale[m], sshift[m]), 0.f);
        }
    }
    float w[9];
    #pragma unroll
    for (int t = 0; t < 9; t++) w[t] = Wdw[n*9 + t];
    __syncthreads();
    float as = 0.f, aq = 0.f;
    for (int i = tid; i < 4096; i += 256) {
        int y = i >> 6, xc = i & 63;
        const float* cptr = &ts[(y+1)*68 + xc + 1];
        float acc;
        acc = w[0]*cptr[-69];
        acc = fmaf(w[1], cptr[-68], acc);
        acc = fmaf(w[2], cptr[-67], acc);
        acc = fmaf(w[3], cptr[-1],  acc);
        acc = fmaf(w[4], cptr[0],   acc);
        acc = fmaf(w[5], cptr[1],   acc);
        acc = fmaf(w[6], cptr[67],  acc);
        acc = fmaf(w[7], cptr[68],  acc);
        acc = fmaf(w[8], cptr[69],  acc);
        g_COUT[(size_t)bn*8192 + y*128 + base + xc] = acc;
        as += acc; aq = fmaf(acc, acc, aq);
    }
    red[tid] = as; redq[tid] = aq;
    __syncthreads();
    for (int off = 128; off > 0; off >>= 1) {
        if (tid < off) { red[tid] += red[tid+off]; redq[tid] += redq[tid+off]; }
        __syncthreads();
    }
    if (tid == 0) { atomicAdd(&g_s3[n], red[0]); atomicAdd(&g_q3[n], redq[0]); }
}

// ---------------- final (R11 version)
__global__ void __launch_bounds__(256) k_final(const float* __restrict__ Wl3,
                                               const float* __restrict__ g3, const float* __restrict__ b3,
                                               const float* __restrict__ gsc, const float* __restrict__ bsc,
                                               float* __restrict__ outp) {
    __shared__ float cs[64*128];
    __shared__ float wst[64*64];
    __shared__ float cscale[128], cshift[128];
    const int bn = blockIdx.x;
    const int half = blockIdx.y;
    const int tid = threadIdx.x;
    const int b = bn >> 5, n = bn & 31;
    if (tid < 128) {
        float m = g_ssc[tid] * (1.f/32768.f);
        float v = g_qsc[tid] * (1.f/32768.f) - m*m;
        float s = gsc[tid] * rsqrtf(v + CEPS);
        cscale[tid] = s;
        cshift[tid] = bsc[tid] - m * s;
    }
    float m3 = g_s3[n] * (1.f/65536.f);
    float v3 = g_q3[n] * (1.f/65536.f) - m3*m3;
    float scale = g3[n] * rsqrtf(v3 + CEPS);
    float shift = b3[n] - m3 * scale;
    const float* cp = g_COUT + (size_t)bn * 8192;
    #pragma unroll
    for (int i = 0; i < 32; i++)
        cs[tid + i*256] = fmaxf(fmaf(cp[tid + i*256], scale, shift), 0.f);
    const float* wp = Wl3 + half*4096;
    #pragma unroll
    for (int i = tid; i < 1024; i += 256) {
        float4 v = ((const float4*)wp)[i];
        int o = i >> 4, m4 = (i & 15) * 4;
        wst[(m4+0)*64 + o] = v.x;
        wst[(m4+1)*64 + o] = v.y;
        wst[(m4+2)*64 + o] = v.z;
        wst[(m4+3)*64 + o] = v.w;
    }
    __syncthreads();
    const int lane = tid & 31, grp = tid >> 5;
    const int d0 = lane * 4;
    u64 acc[4][4];
    #pragma unroll
    for (int i = 0; i < 4; i++)
        #pragma unroll
        for (int j = 0; j < 4; j++) acc[i][j] = 0ull;
    #pragma unroll 4
    for (int m = 0; m < 64; m++) {
        float4 xv = *(const float4*)&cs[m*128 + d0];
        u64 xd0 = pk2(xv.x, xv.x), xd1 = pk2(xv.y, xv.y);
        u64 xd2 = pk2(xv.z, xv.z), xd3 = pk2(xv.w, xv.w);
        ulonglong2 w01 = *(const ulonglong2*)&wst[m*64 + grp*8];
        ulonglong2 w23 = *(const ulonglong2*)&wst[m*64 + grp*8 + 4];
        acc[0][0]=fma2(w01.x,xd0,acc[0][0]); acc[0][1]=fma2(w01.x,xd1,acc[0][1]);
        acc[0][2]=fma2(w01.x,xd2,acc[0][2]); acc[0][3]=fma2(w01.x,xd3,acc[0][3]);
        acc[1][0]=fma2(w01.y,xd0,acc[1][0]); acc[1][1]=fma2(w01.y,xd1,acc[1][1]);
        acc[1][2]=fma2(w01.y,xd2,acc[1][2]); acc[1][3]=fma2(w01.y,xd3,acc[1][3]);
        acc[2][0]=fma2(w23.x,xd0,acc[2][0]); acc[2][1]=fma2(w23.x,xd1,acc[2][1]);
        acc[2][2]=fma2(w23.x,xd2,acc[2][2]); acc[2][3]=fma2(w23.x,xd3,acc[2][3]);
        acc[3][0]=fma2(w23.y,xd0,acc[3][0]); acc[3][1]=fma2(w23.y,xd1,acc[3][1]);
        acc[3][2]=fma2(w23.y,xd2,acc[3][2]); acc[3][3]=fma2(w23.y,xd3,acc[3][3]);
    }
    #pragma unroll
    for (int kp = 0; kp < 4; kp++) {
        int o = half*64 + grp*8 + kp*2;
        float lo0,hi0,lo1,hi1,lo2,hi2,lo3,hi3;
        upk2(acc[kp][0], lo0, hi0); upk2(acc[kp][1], lo1, hi1);
        upk2(acc[kp][2], lo2, hi2); upk2(acc[kp][3], lo3, hi3);
        const float* scp0 = g_YSC + ((((size_t)b*128 + o)*32 + n) << 7);
        const float* scp1 = g_YSC + ((((size_t)b*128 + o + 1)*32 + n) << 7);
        float* op0 = outp + ((((size_t)b*32 + n)*128 + o) << 7);
        float* op1 = outp + ((((size_t)b*32 + n)*128 + o + 1) << 7);
        float4 s0 = *(const float4*)&scp0[d0];
        float4 s1 = *(const float4*)&scp1[d0];
        float sca0 = cscale[o],   shf0 = cshift[o];
        float sca1 = cscale[o+1], shf1 = cshift[o+1];
        *(float4*)&op0[d0] = make_float4(lo0 + fmaf(s0.x, sca0, shf0),
                                         lo1 + fmaf(s0.y, sca0, shf0),
                                         lo2 + fmaf(s0.z, sca0, shf0),
                                         lo3 + fmaf(s0.w, sca0, shf0));
        *(float4*)&op1[d0] = make_float4(hi0 + fmaf(s1.x, sca1, shf1),
                                         hi1 + fmaf(s1.y, sca1, shf1),
                                         hi2 + fmaf(s1.z, sca1, shf1),
                                         hi3 + fmaf(s1.w, sca1, shf1));
    }
}

// ---------------- launcher: forked graph (main + side stream) ----------------
extern "C" void kernel_launch(void* const* d_in, const int* in_sizes, int n_in,
                              void* d_out, int out_size) {
    const float* x    = (const float*)d_in[0];
    const float* Wsc  = (const float*)d_in[1];
    const float* gsc  = (const float*)d_in[2];
    const float* bsc  = (const float*)d_in[3];
    const float* Wl1  = (const float*)d_in[4];
    const float* g1   = (const float*)d_in[5];
    const float* b1   = (const float*)d_in[6];
    const float* Wfc1 = (const float*)d_in[7];
    const float* Wfc2 = (const float*)d_in[8];
    const float* g2   = (const float*)d_in[9];
    const float* b2   = (const float*)d_in[10];
    const float* Wdw  = (const float*)d_in[11];
    const float* g3   = (const float*)d_in[12];
    const float* b3   = (const float*)d_in[13];
    const float* Wl3  = (const float*)d_in[14];
    float* outp = (float*)d_out;

    float *hs, *e2;
    cudaGetSymbolAddress((void**)&hs, g_HS);
    cudaGetSymbolAddress((void**)&e2, g_E2);

    cudaStream_t side;
    cudaStreamCreateWithFlags(&side, cudaStreamNonBlocking);
    cudaEvent_t ev0, evW, evY;
    cudaEventCreateWithFlags(&ev0, cudaEventDisableTiming);
    cudaEventCreateWithFlags(&evW, cudaEventDisableTiming);
    cudaEventCreateWithFlags(&evY, cudaEventDisableTiming);

    // pre-fork: zero all stat accumulators
    k_zero<<<1, 256>>>();
    cudaEventRecord(ev0, 0);
    cudaStreamWaitEvent(side, ev0, 0);

    // side branch: WR reduce, then YSC (shortcut) matmul
    k_wred<<<64, 256, 0, side>>>(Wfc1);
    cudaEventRecord(evW, side);
    k1_matmul<<<dim3(256, 2), 256, 0, side>>>(x, Wsc, 0);   // chunks 0,1 -> YSC
    cudaEventRecord(evY, side);

    // main branch
    k1_matmul<<<256, 256>>>(x, Wl1, 2);                     // chunk 2 -> X1
    k_att1<<<512, 256>>>(g1, b1);
    cudaStreamWaitEvent(0, evW, 0);
    k_hsmall<<<64, 256>>>();
    k_gemm<<<dim3(16, 8, 4), 128>>>(hs, Wfc2, e2, 1024, 512, 128);
    k_att2<<<512, 256>>>(g1, b1);
    k_conv<<<dim3(256, 2), 256>>>(Wdw, g2, b2);
    cudaStreamWaitEvent(0, evY, 0);
    k_final<<<dim3(256, 2), 256>>>(Wl3, g3, b3, gsc, bsc, outp);

    cudaEventDestroy(ev0);
    cudaEventDestroy(evW);
    cudaEventDestroy(evY);
    cudaStreamDestroy(side);
}